// round 11
// baseline (speedup 1.0000x reference)
#include <cuda_runtime.h>
#include <cuda_fp16.h>
#include <cstdint>

#define DIM    64
#define CODES  512
#define NTOK   262144
#define TPB    256
#define TILTOK 128
#define NTILE  (NTOK / TILTOK)   // 2048
#define GRID2  152

// Output layout (float32, concatenated tuple)
#define OFF_Q    0L
#define OFF_QL   16777216L
#define OFF_IDX  16777217L
#define OFF_CL   17039361L
#define OFF_EMB  17039362L
#define OFF_N    17072130L
#define OFF_M    17072642L

// vq_mma smem byte offsets
#define SMB_A    0          // A permuted fp16: 32KB (64 slots x 512B)
#define SMB_B    32768      // B resident: 128KB
#define SMB_N    163840     // norms: 512 f
#define SMB_XN   165888     // xnorm: 128 f
#define SMB_RB   166400     // best: 512 f
#define SMB_RI   168448     // idx: 512 i
#define SMEM_BYTES 170496

__device__ float  g_embT[CODES * DIM];   // [c][d] fp32 for gather
__device__ uint4  g_bperm[8192];         // packed fp16-split B fragments (hi,hi,lo,lo)
__device__ float  g_norm[CODES];
__device__ float  g_ni[CODES];
__device__ float  g_eofxT[CODES * DIM];  // [c][d]
__device__ float  g_loss;
__device__ int    g_idx[NTOK];
__device__ float  g_Ns[CODES];

// ---------------- helpers ----------------
__device__ __forceinline__ void red_f(float* p, float v) {
    asm volatile("red.global.add.f32 [%0], %1;" :: "l"(p), "f"(v) : "memory");
}
__device__ __forceinline__ void red_v2(float* p, float a, float b) {
    asm volatile("red.global.add.v2.f32 [%0], {%1, %2};" :: "l"(p), "f"(a), "f"(b) : "memory");
}
__device__ __forceinline__ void mma_f16(float* d, const uint4 a, uint32_t b0, uint32_t b1) {
    asm("mma.sync.aligned.m16n8k16.row.col.f32.f16.f16.f32 "
        "{%0,%1,%2,%3}, {%4,%5,%6,%7}, {%8,%9}, {%0,%1,%2,%3};"
        : "+f"(d[0]), "+f"(d[1]), "+f"(d[2]), "+f"(d[3])
        : "r"(a.x), "r"(a.y), "r"(a.z), "r"(a.w), "r"(b0), "r"(b1));
}
__device__ __forceinline__ uint32_t smem_u32(const void* p) {
    uint32_t a;
    asm("{ .reg .u64 t; cvta.to.shared.u64 t, %1; cvt.u32.u64 %0, t; }" : "=r"(a) : "l"(p));
    return a;
}
__device__ __forceinline__ void cp16(uint32_t dst, const void* src) {
    asm volatile("cp.async.cg.shared.global [%0], [%1], 16;" :: "r"(dst), "l"(src) : "memory");
}
#define CP_COMMIT() asm volatile("cp.async.commit_group;" ::: "memory")
#define CP_WAIT0()  asm volatile("cp.async.wait_group 0;" ::: "memory")

__device__ __forceinline__ void split1(float v, __half& h, __half& l) {
    h = __float2half_rn(v);
    l = __float2half_rn(v - __half2float(h));
}

// ---------------- k1: zero + norms + transpose + packed fp16-split B ----------------
__global__ void vq_split(const float* __restrict__ emb) {
    const int idx = blockIdx.x * 512 + threadIdx.x;   // 0..32767

    g_eofxT[idx] = 0.f;
    if (idx < CODES) g_ni[idx] = 0.f;
    if (idx == 0) g_loss = 0.f;

    // transposed fp32 copy for gather
    { int c = idx >> 6, d = idx & 63; g_embT[idx] = emb[d * CODES + c]; }

    // exact code norms
    if (idx < CODES) {
        float s = 0.f;
        #pragma unroll
        for (int d = 0; d < DIM; d++) {
            float v = emb[d * CODES + idx];
            s = fmaf(v, v, s);
        }
        g_norm[idx] = s;
    }

    // B fragment slots: idx = (cfrag*4 + ks)*32 + lane, cfrag = code>>3 (0..63)
    // uint4 = {b0_hi, b1_hi, b0_lo, b1_lo}, each fp16x2
    if (idx < 8192) {
        int l  = idx & 31;
        int ks = (idx >> 5) & 3;
        int cf = idx >> 7;
        int n  = cf * 8 + (l >> 2);
        int k0 = ks * 16 + 2 * (l & 3);
        float v00 = emb[k0 * CODES + n];
        float v01 = emb[(k0 + 1) * CODES + n];
        float v10 = emb[(k0 + 8) * CODES + n];
        float v11 = emb[(k0 + 9) * CODES + n];
        __half h00, l00, h01, l01, h10, l10, h11, l11;
        split1(v00, h00, l00); split1(v01, h01, l01);
        split1(v10, h10, l10); split1(v11, h11, l11);
        uint4 o;
        { __half2 t = __halves2half2(h00, h01); o.x = *reinterpret_cast<uint32_t*>(&t); }
        { __half2 t = __halves2half2(h10, h11); o.y = *reinterpret_cast<uint32_t*>(&t); }
        { __half2 t = __halves2half2(l00, l01); o.z = *reinterpret_cast<uint32_t*>(&t); }
        { __half2 t = __halves2half2(l10, l11); o.w = *reinterpret_cast<uint32_t*>(&t); }
        g_bperm[idx] = o;
    }
}

// ---------------- k2: persistent fp16 4-term split mma.sync assign ----------------
extern __shared__ char sm[];

__global__ void __launch_bounds__(TPB, 1)
vq_mma(const float* __restrict__ x, float* __restrict__ out) {
    const int tid  = threadIdx.x;
    const int lane = tid & 31, wid = tid >> 5;
    const int tg = wid & 1;          // token group (64 tokens)
    const int cg = wid >> 1;         // code group (128 codes)
    const int g  = lane >> 2;
    const int tig = lane & 3;

    float* sN  = (float*)(sm + SMB_N);
    float* sXn = (float*)(sm + SMB_XN);
    float* sRb = (float*)(sm + SMB_RB);
    int*   sRi = (int*)(sm + SMB_RI);
    const uint32_t smbase = smem_u32(sm);

    // ---- one-time: norms + resident B (128KB) ----
    sN[tid] = g_norm[tid];
    sN[256 + tid] = g_norm[256 + tid];
    {
        const char* src = (const char*)g_bperm;
        #pragma unroll
        for (int i = 0; i < 32; i++) {
            int off = (i * TPB + tid) * 16;
            cp16(smbase + SMB_B + off, src + off);
        }
        CP_COMMIT();
        CP_WAIT0();
    }
    __syncthreads();

    for (int tile = blockIdx.x; tile < NTILE; tile += GRID2) {
        const int gtok0 = tile * TILTOK;

        // ---- load x (half token per thread), xnorm, write permuted A ----
        {
            const int T = tid >> 1, half = tid & 1;
            const int ttg = T >> 6, r = T & 63;
            const int mf = r >> 4, rr = r & 15;
            const int gg = rr & 7, row8 = rr >> 3;
            const uint32_t lanebase = (uint32_t)(gg * 64);
            const float4* xg = (const float4*)(x + (size_t)(gtok0 + T) * DIM + half * 32);
            float xn = 0.f;
            #pragma unroll
            for (int j = 0; j < 8; j++) {
                float4 v = xg[j];
                xn = fmaf(v.x, v.x, xn); xn = fmaf(v.y, v.y, xn);
                xn = fmaf(v.z, v.z, xn); xn = fmaf(v.w, v.w, xn);
                #pragma unroll
                for (int pp = 0; pp < 2; pp++) {
                    int k = half * 32 + 4 * j + 2 * pp;
                    float a = pp ? v.z : v.x;
                    float b = pp ? v.w : v.y;
                    int ks = k >> 4, kk = k & 15;
                    int sel8 = kk >> 3, ktig = (kk & 7) >> 1;
                    int areg = sel8 * 2 + row8;
                    __half ha, la, hb, lb;
                    split1(a, ha, la); split1(b, hb, lb);
                    int slot = ((ttg * 4 + mf) * 4 + ks) * 2;
                    uint32_t byte = (uint32_t)slot * 512 + lanebase + (uint32_t)ktig * 16 + (uint32_t)areg * 4;
                    __half2 hh = __halves2half2(ha, hb);
                    __half2 ll = __halves2half2(la, lb);
                    *(uint32_t*)(sm + SMB_A + byte)       = *reinterpret_cast<uint32_t*>(&hh);
                    *(uint32_t*)(sm + SMB_A + byte + 512) = *reinterpret_cast<uint32_t*>(&ll);
                }
            }
            xn += __shfl_xor_sync(0xffffffffu, xn, 1);
            if (half == 0) sXn[T] = xn;
        }
        __syncthreads();

        // ---- mainloop: warp covers 64 tokens x 128 codes ----
        float best[8];  int bidx[8];
        #pragma unroll
        for (int s = 0; s < 8; s++) { best[s] = 3.402823466e38f; bidx[s] = 0; }

        #pragma unroll
        for (int ch = 0; ch < 4; ch++) {
            float acc[4][4][4];
            #pragma unroll
            for (int mf = 0; mf < 4; mf++)
                #pragma unroll
                for (int j = 0; j < 4; j++)
                    #pragma unroll
                    for (int q = 0; q < 4; q++) acc[mf][j][q] = 0.f;

            #pragma unroll
            for (int ks = 0; ks < 4; ks++) {
                uint4 af[4][2];
                #pragma unroll
                for (int mf = 0; mf < 4; mf++)
                    #pragma unroll
                    for (int hl = 0; hl < 2; hl++)
                        af[mf][hl] = *(const uint4*)(sm + SMB_A +
                            (((tg * 4 + mf) * 4 + ks) * 2 + hl) * 512 + lane * 16);
                uint4 bf[4];
                #pragma unroll
                for (int j = 0; j < 4; j++)
                    bf[j] = *(const uint4*)(sm + SMB_B +
                        ((cg * 16 + ch * 4 + j) * 4 + ks) * 512 + lane * 16);
                #pragma unroll
                for (int mf = 0; mf < 4; mf++) {
                    #pragma unroll
                    for (int j = 0; j < 4; j++) {
                        mma_f16(acc[mf][j], af[mf][0], bf[j].x, bf[j].y);  // xh·eh
                        mma_f16(acc[mf][j], af[mf][0], bf[j].z, bf[j].w);  // xh·el
                        mma_f16(acc[mf][j], af[mf][1], bf[j].x, bf[j].y);  // xl·eh
                        mma_f16(acc[mf][j], af[mf][1], bf[j].z, bf[j].w);  // xl·el
                    }
                }
            }
            // epilogue chunk: dist + running argmin (codes ascending)
            #pragma unroll
            for (int j = 0; j < 4; j++) {
                int c0 = cg * 128 + (ch * 4 + j) * 8 + 2 * tig;
                float n0 = sN[c0], n1 = sN[c0 + 1];
                #pragma unroll
                for (int mf = 0; mf < 4; mf++) {
                    float d00 = fmaf(-2.f, acc[mf][j][0], n0);
                    float d01 = fmaf(-2.f, acc[mf][j][1], n1);
                    float d10 = fmaf(-2.f, acc[mf][j][2], n0);
                    float d11 = fmaf(-2.f, acc[mf][j][3], n1);
                    int s0 = mf * 2, s1 = mf * 2 + 1;
                    if (d00 < best[s0]) { best[s0] = d00; bidx[s0] = c0; }
                    if (d01 < best[s0]) { best[s0] = d01; bidx[s0] = c0 + 1; }
                    if (d10 < best[s1]) { best[s1] = d10; bidx[s1] = c0; }
                    if (d11 < best[s1]) { best[s1] = d11; bidx[s1] = c0 + 1; }
                }
            }
        }

        // reduce across tig lanes (same tokens), tie -> min index
        #pragma unroll
        for (int off = 1; off <= 2; off <<= 1) {
            #pragma unroll
            for (int s = 0; s < 8; s++) {
                float ob = __shfl_xor_sync(0xffffffffu, best[s], off);
                int   oc = __shfl_xor_sync(0xffffffffu, bidx[s], off);
                if (ob < best[s] || (ob == best[s] && oc < bidx[s])) { best[s] = ob; bidx[s] = oc; }
            }
        }
        if (tig == 0) {
            #pragma unroll
            for (int s = 0; s < 8; s++) {
                int mf = s >> 1, rh = s & 1;
                int t = tg * 64 + mf * 16 + rh * 8 + g;
                sRb[t * 4 + cg] = best[s];
                sRi[t * 4 + cg] = bidx[s];
            }
        }
        __syncthreads();

        // ---- per-token tail (tid < 128) ----
        if (tid < TILTOK) {
            const int t = tid;
            float bd = sRb[t * 4]; int bc = sRi[t * 4];
            #pragma unroll
            for (int s = 1; s < 4; s++) {
                float ob = sRb[t * 4 + s]; int oc = sRi[t * 4 + s];
                if (ob < bd || (ob == bd && oc < bc)) { bd = ob; bc = oc; }
            }
            const int gt = gtok0 + t;
            g_idx[gt] = bc;
            out[OFF_IDX + gt] = (float)bc;
            red_f(&g_ni[bc], 1.0f);
            float l = bd + sXn[t];
            #pragma unroll
            for (int o = 16; o; o >>= 1) l += __shfl_xor_sync(0xffffffffu, l, o);
            if ((tid & 31) == 0) red_f(&g_loss, l);

            float* gb = g_eofxT + bc * DIM;
            const float4* xg = (const float4*)(x + (size_t)gt * DIM);
            #pragma unroll
            for (int j = 0; j < 16; j++) {
                float4 v = xg[j];
                red_v2(gb + 4 * j, v.x, v.y);
                red_v2(gb + 4 * j + 2, v.z, v.w);
            }
        }
        __syncthreads();
    }
}

// ---------------- k3: quantize gather (warp per token group) ----------------
__global__ void __launch_bounds__(256)
vq_gather(float* __restrict__ out) {
    extern __shared__ float sE[];   // [512][64]
    const int tid = threadIdx.x;
    {
        const float4* src = (const float4*)g_embT;
        float4* dst = (float4*)sE;
        #pragma unroll
        for (int it = 0; it < 32; it++) dst[it * 256 + tid] = src[it * 256 + tid];
    }
    __syncthreads();
    const int warp = tid >> 5, lane = tid & 31;
    const int tbase = blockIdx.x * 1024 + warp * 128;
    int my[4];
    #pragma unroll
    for (int i = 0; i < 4; i++) my[i] = g_idx[tbase + i * 32 + lane];
    #pragma unroll
    for (int i = 0; i < 4; i++) {
        #pragma unroll 8
        for (int s = 0; s < 32; s++) {
            int c = __shfl_sync(0xffffffffu, my[i], s);
            float2 qv = *(const float2*)&sE[c * DIM + lane * 2];
            *(float2*)&out[OFF_Q + (size_t)(tbase + i * 32 + s) * DIM + lane * 2] = qv;
        }
    }
}

// ---------------- k4a: N_new, smoothing denom, losses ----------------
__global__ void vq_n(const float* __restrict__ Nin, float* __restrict__ out) {
    __shared__ float red[CODES];
    const int c = threadIdx.x;
    const float OMD = 1.0f - 0.99f;
    float Nn = fmaf(Nin[c], 0.99f, OMD * g_ni[c]);
    out[OFF_N + c] = Nn;
    red[c] = Nn;
    __syncthreads();
    for (int s = CODES / 2; s > 0; s >>= 1) {
        if (c < s) red[c] += red[c + s];
        __syncthreads();
    }
    float n = red[0];
    g_Ns[c] = (Nn + 1e-5f) / (n + CODES * 1e-5f) * n;
    if (c == 0) {
        float l = g_loss * (1.0f / 16777216.0f);
        out[OFF_QL] = l;
        out[OFF_CL] = l;
    }
}

// ---------------- k4b: M_new + embedding_new ----------------
__global__ void vq_m(const float* __restrict__ Min, float* __restrict__ out) {
    const int idx = blockIdx.x * 512 + threadIdx.x;   // 32768
    const int d = idx >> 9, c = idx & (CODES - 1);
    const float OMD = 1.0f - 0.99f;
    float Mn = fmaf(Min[idx], 0.99f, OMD * g_eofxT[c * DIM + d]);
    out[OFF_M + idx] = Mn;
    out[OFF_EMB + idx] = Mn / g_Ns[c];
}

extern "C" void kernel_launch(void* const* d_in, const int* in_sizes, int n_in,
                              void* d_out, int out_size) {
    const float* x   = (const float*)d_in[0];
    const float* emb = (const float*)d_in[1];
    const float* N   = (const float*)d_in[2];
    const float* M   = (const float*)d_in[3];
    float* out = (float*)d_out;

    cudaFuncSetAttribute(vq_mma, cudaFuncAttributeMaxDynamicSharedMemorySize, SMEM_BYTES);
    cudaFuncSetAttribute(vq_gather, cudaFuncAttributeMaxDynamicSharedMemorySize, 131072);

    vq_split<<<64, 512>>>(emb);
    vq_mma<<<GRID2, TPB, SMEM_BYTES>>>(x, out);
    vq_gather<<<256, 256, 131072>>>(out);
    vq_n<<<1, CODES>>>(N, out);
    vq_m<<<64, 512>>>(M, out);
}

// round 12
// speedup vs baseline: 1.0378x; 1.0378x over previous
#include <cuda_runtime.h>
#include <cuda_fp16.h>
#include <cstdint>

#define DIM    64
#define CODES  512
#define NTOK   262144
#define TPB    256
#define TILTOK 128
#define NTILE  (NTOK / TILTOK)   // 2048
#define GRID2  152
#define FLTMAX 3.402823466e38f

// Output layout (float32, concatenated tuple)
#define OFF_Q    0L
#define OFF_QL   16777216L
#define OFF_IDX  16777217L
#define OFF_CL   17039361L
#define OFF_EMB  17039362L
#define OFF_N    17072130L
#define OFF_M    17072642L

// vq_mma smem byte offsets
#define SMB_A    0          // A permuted fp16: 32KB
#define SMB_B    32768      // B resident: 128KB
#define SMB_N    163840     // norms: 512 f
#define SMB_XN   165888     // xnorm: 128 f
#define SMB_RB   166400     // best: 512 f
#define SMB_RB2  168448     // 2nd best: 512 f
#define SMB_RI   170496     // idx: 512 i
#define SMEM_BYTES 172544

__device__ float  g_embT[CODES * DIM];   // [c][d] fp32 (gather + rescan)
__device__ uint4  g_bperm[8192];         // packed fp16-split B fragments (hi,hi,lo,lo)
__device__ float  g_norm[CODES];
__device__ float  g_ni[CODES];
__device__ float  g_eofxT[CODES * DIM];  // [c][d]
__device__ float  g_loss;
__device__ int    g_idx[NTOK];

// ---------------- helpers ----------------
__device__ __forceinline__ void red_f(float* p, float v) {
    asm volatile("red.global.add.f32 [%0], %1;" :: "l"(p), "f"(v) : "memory");
}
__device__ __forceinline__ void red_v2(float* p, float a, float b) {
    asm volatile("red.global.add.v2.f32 [%0], {%1, %2};" :: "l"(p), "f"(a), "f"(b) : "memory");
}
__device__ __forceinline__ void mma_f16(float* d, const uint4 a, uint32_t b0, uint32_t b1) {
    asm("mma.sync.aligned.m16n8k16.row.col.f32.f16.f16.f32 "
        "{%0,%1,%2,%3}, {%4,%5,%6,%7}, {%8,%9}, {%0,%1,%2,%3};"
        : "+f"(d[0]), "+f"(d[1]), "+f"(d[2]), "+f"(d[3])
        : "r"(a.x), "r"(a.y), "r"(a.z), "r"(a.w), "r"(b0), "r"(b1));
}
__device__ __forceinline__ uint32_t smem_u32(const void* p) {
    uint32_t a;
    asm("{ .reg .u64 t; cvta.to.shared.u64 t, %1; cvt.u32.u64 %0, t; }" : "=r"(a) : "l"(p));
    return a;
}
__device__ __forceinline__ void cp16(uint32_t dst, const void* src) {
    asm volatile("cp.async.cg.shared.global [%0], [%1], 16;" :: "r"(dst), "l"(src) : "memory");
}
#define CP_COMMIT() asm volatile("cp.async.commit_group;" ::: "memory")
#define CP_WAIT0()  asm volatile("cp.async.wait_group 0;" ::: "memory")

__device__ __forceinline__ void split1(float v, __half& h, __half& l) {
    h = __float2half_rn(v);
    l = __float2half_rn(v - __half2float(h));
}

// ---------------- k1: zero + norms + transpose + packed fp16-split B ----------------
__global__ void vq_split(const float* __restrict__ emb) {
    const int idx = blockIdx.x * 512 + threadIdx.x;   // 0..32767

    g_eofxT[idx] = 0.f;
    if (idx < CODES) g_ni[idx] = 0.f;
    if (idx == 0) g_loss = 0.f;

    { int c = idx >> 6, d = idx & 63; g_embT[idx] = emb[d * CODES + c]; }

    if (idx < CODES) {
        float s = 0.f;
        #pragma unroll
        for (int d = 0; d < DIM; d++) {
            float v = emb[d * CODES + idx];
            s = fmaf(v, v, s);
        }
        g_norm[idx] = s;
    }

    // B fragment slots: idx = (cfrag*4 + ks)*32 + lane, cfrag = code>>3
    if (idx < 8192) {
        int l  = idx & 31;
        int ks = (idx >> 5) & 3;
        int cf = idx >> 7;
        int n  = cf * 8 + (l >> 2);
        int k0 = ks * 16 + 2 * (l & 3);
        float v00 = emb[k0 * CODES + n];
        float v01 = emb[(k0 + 1) * CODES + n];
        float v10 = emb[(k0 + 8) * CODES + n];
        float v11 = emb[(k0 + 9) * CODES + n];
        __half h00, l00, h01, l01, h10, l10, h11, l11;
        split1(v00, h00, l00); split1(v01, h01, l01);
        split1(v10, h10, l10); split1(v11, h11, l11);
        uint4 o;
        { __half2 t = __halves2half2(h00, h01); o.x = *reinterpret_cast<uint32_t*>(&t); }
        { __half2 t = __halves2half2(h10, h11); o.y = *reinterpret_cast<uint32_t*>(&t); }
        { __half2 t = __halves2half2(l00, l01); o.z = *reinterpret_cast<uint32_t*>(&t); }
        { __half2 t = __halves2half2(l10, l11); o.w = *reinterpret_cast<uint32_t*>(&t); }
        g_bperm[idx] = o;
    }
}

// ---------------- k2: persistent fp16 3-term split + bound-verified argmin ----------------
extern __shared__ char sm[];

__global__ void __launch_bounds__(TPB, 1)
vq_mma(const float* __restrict__ x, float* __restrict__ out) {
    const int tid  = threadIdx.x;
    const int lane = tid & 31, wid = tid >> 5;
    const int tg = wid & 1;          // token group (64 tokens)
    const int cg = wid >> 1;         // code group (128 codes)
    const int g  = lane >> 2;
    const int tig = lane & 3;

    float* sN   = (float*)(sm + SMB_N);
    float* sXn  = (float*)(sm + SMB_XN);
    float* sRb  = (float*)(sm + SMB_RB);
    float* sRb2 = (float*)(sm + SMB_RB2);
    int*   sRi  = (int*)(sm + SMB_RI);
    const uint32_t smbase = smem_u32(sm);

    // ---- one-time: norms + resident B (128KB) ----
    sN[tid] = g_norm[tid];
    sN[256 + tid] = g_norm[256 + tid];
    {
        const char* src = (const char*)g_bperm;
        #pragma unroll
        for (int i = 0; i < 32; i++) {
            int off = (i * TPB + tid) * 16;
            cp16(smbase + SMB_B + off, src + off);
        }
        CP_COMMIT();
        CP_WAIT0();
    }
    __syncthreads();
    // max code norm (for the safety bound)
    sRb[tid] = fmaxf(sN[tid], sN[256 + tid]);
    __syncthreads();
    for (int s = 128; s > 0; s >>= 1) {
        if (tid < s) sRb[tid] = fmaxf(sRb[tid], sRb[tid + s]);
        __syncthreads();
    }
    const float maxn2 = sRb[0];
    __syncthreads();

    for (int tile = blockIdx.x; tile < NTILE; tile += GRID2) {
        const int gtok0 = tile * TILTOK;

        // ---- load x (half token per thread), xnorm, write permuted A ----
        {
            const int T = tid >> 1, half = tid & 1;
            const int ttg = T >> 6, r = T & 63;
            const int mf = r >> 4, rr = r & 15;
            const int gg = rr & 7, row8 = rr >> 3;
            const uint32_t lanebase = (uint32_t)(gg * 64);
            const float4* xg = (const float4*)(x + (size_t)(gtok0 + T) * DIM + half * 32);
            float xn = 0.f;
            #pragma unroll
            for (int j = 0; j < 8; j++) {
                float4 v = xg[j];
                xn = fmaf(v.x, v.x, xn); xn = fmaf(v.y, v.y, xn);
                xn = fmaf(v.z, v.z, xn); xn = fmaf(v.w, v.w, xn);
                #pragma unroll
                for (int pp = 0; pp < 2; pp++) {
                    int k = half * 32 + 4 * j + 2 * pp;
                    float a = pp ? v.z : v.x;
                    float b = pp ? v.w : v.y;
                    int ks = k >> 4, kk = k & 15;
                    int sel8 = kk >> 3, ktig = (kk & 7) >> 1;
                    int areg = sel8 * 2 + row8;
                    __half ha, la, hb, lb;
                    split1(a, ha, la); split1(b, hb, lb);
                    int slot = ((ttg * 4 + mf) * 4 + ks) * 2;
                    uint32_t byte = (uint32_t)slot * 512 + lanebase + (uint32_t)ktig * 16 + (uint32_t)areg * 4;
                    __half2 hh = __halves2half2(ha, hb);
                    __half2 ll = __halves2half2(la, lb);
                    *(uint32_t*)(sm + SMB_A + byte)       = *reinterpret_cast<uint32_t*>(&hh);
                    *(uint32_t*)(sm + SMB_A + byte + 512) = *reinterpret_cast<uint32_t*>(&ll);
                }
            }
            xn += __shfl_xor_sync(0xffffffffu, xn, 1);
            if (half == 0) sXn[T] = xn;
        }
        __syncthreads();

        // ---- mainloop: warp covers 64 tokens x 128 codes; 3 split terms ----
        float best[8], bsec[8]; int bidx[8];
        #pragma unroll
        for (int s = 0; s < 8; s++) { best[s] = FLTMAX; bsec[s] = FLTMAX; bidx[s] = 0; }

        #pragma unroll
        for (int ch = 0; ch < 4; ch++) {
            float acc[4][4][4];
            #pragma unroll
            for (int mf = 0; mf < 4; mf++)
                #pragma unroll
                for (int j = 0; j < 4; j++)
                    #pragma unroll
                    for (int q = 0; q < 4; q++) acc[mf][j][q] = 0.f;

            #pragma unroll
            for (int ks = 0; ks < 4; ks++) {
                uint4 af[4][2];
                #pragma unroll
                for (int mf = 0; mf < 4; mf++)
                    #pragma unroll
                    for (int hl = 0; hl < 2; hl++)
                        af[mf][hl] = *(const uint4*)(sm + SMB_A +
                            (((tg * 4 + mf) * 4 + ks) * 2 + hl) * 512 + lane * 16);
                uint4 bf[4];
                #pragma unroll
                for (int j = 0; j < 4; j++)
                    bf[j] = *(const uint4*)(sm + SMB_B +
                        ((cg * 16 + ch * 4 + j) * 4 + ks) * 512 + lane * 16);
                #pragma unroll
                for (int mf = 0; mf < 4; mf++) {
                    #pragma unroll
                    for (int j = 0; j < 4; j++) {
                        mma_f16(acc[mf][j], af[mf][0], bf[j].x, bf[j].y);  // xh·eh
                        mma_f16(acc[mf][j], af[mf][0], bf[j].z, bf[j].w);  // xh·el
                        mma_f16(acc[mf][j], af[mf][1], bf[j].x, bf[j].y);  // xl·eh
                    }
                }
            }
            // epilogue chunk: dist + top-2 tracking
            #pragma unroll
            for (int j = 0; j < 4; j++) {
                int c0 = cg * 128 + (ch * 4 + j) * 8 + 2 * tig;
                float n0 = sN[c0], n1 = sN[c0 + 1];
                #pragma unroll
                for (int mf = 0; mf < 4; mf++) {
                    float dv[4];
                    dv[0] = fmaf(-2.f, acc[mf][j][0], n0);
                    dv[1] = fmaf(-2.f, acc[mf][j][1], n1);
                    dv[2] = fmaf(-2.f, acc[mf][j][2], n0);
                    dv[3] = fmaf(-2.f, acc[mf][j][3], n1);
                    #pragma unroll
                    for (int q = 0; q < 4; q++) {
                        int s = mf * 2 + (q >> 1);
                        int c = c0 + (q & 1);
                        if (dv[q] < best[s]) { bsec[s] = best[s]; best[s] = dv[q]; bidx[s] = c; }
                        else if (dv[q] < bsec[s]) bsec[s] = dv[q];
                    }
                }
            }
        }

        // merge across tig lanes (same tokens)
        #pragma unroll
        for (int off = 1; off <= 2; off <<= 1) {
            #pragma unroll
            for (int s = 0; s < 8; s++) {
                float ob  = __shfl_xor_sync(0xffffffffu, best[s], off);
                int   oc  = __shfl_xor_sync(0xffffffffu, bidx[s], off);
                float ob2 = __shfl_xor_sync(0xffffffffu, bsec[s], off);
                if (ob < best[s] || (ob == best[s] && oc < bidx[s])) {
                    bsec[s] = fminf(best[s], ob2); best[s] = ob; bidx[s] = oc;
                } else {
                    bsec[s] = fminf(bsec[s], ob);
                }
            }
        }
        if (tig == 0) {
            #pragma unroll
            for (int s = 0; s < 8; s++) {
                int mf = s >> 1, rh = s & 1;
                int t = tg * 64 + mf * 16 + rh * 8 + g;
                sRb[t * 4 + cg]  = best[s];
                sRb2[t * 4 + cg] = bsec[s];
                sRi[t * 4 + cg]  = bidx[s];
            }
        }
        __syncthreads();

        // ---- per-token tail (tid < 128) ----
        if (tid < TILTOK) {
            const int t = tid;
            float b1 = sRb[t * 4]; int i1 = sRi[t * 4]; float b2 = sRb2[t * 4];
            #pragma unroll
            for (int s = 1; s < 4; s++) {
                float ob = sRb[t * 4 + s]; int oc = sRi[t * 4 + s]; float ob2 = sRb2[t * 4 + s];
                if (ob < b1 || (ob == b1 && oc < i1)) { b2 = fminf(b1, ob2); b1 = ob; i1 = oc; }
                else b2 = fminf(b2, ob);
            }
            const float xn = sXn[t];
            // safety bound: 2^-18 * ||x|| * max||e||
            const float B = 3.814697266e-6f * sqrtf(xn * maxn2);
            float bd = b1; int bc = i1;
            bool flag = (b2 - b1) < 2.f * B;

            unsigned msk = __ballot_sync(0xffffffffu, flag);
            while (msk) {
                int ld = __ffs(msk) - 1; msk &= msk - 1;
                int rt = (tid & ~31) + ld;                // flagged token (tail thread id == token)
                const float4* xg4 = (const float4*)(x + (size_t)(gtok0 + rt) * DIM);
                float bdw = FLTMAX; int bcw = 0;
                for (int ci = 0; ci < 16; ci++) {
                    int c = ci * 32 + (tid & 31);
                    const float4* eg4 = (const float4*)(g_embT + c * DIM);
                    float dot = 0.f;
                    #pragma unroll
                    for (int j = 0; j < 16; j++) {
                        float4 xv4 = xg4[j]; float4 ev4 = eg4[j];
                        dot = fmaf(xv4.x, ev4.x, dot);
                        dot = fmaf(xv4.y, ev4.y, dot);
                        dot = fmaf(xv4.z, ev4.z, dot);
                        dot = fmaf(xv4.w, ev4.w, dot);
                    }
                    float dd = fmaf(-2.f, dot, sN[c]);
                    if (dd < bdw) { bdw = dd; bcw = c; }
                }
                #pragma unroll
                for (int off = 16; off; off >>= 1) {
                    float ob = __shfl_xor_sync(0xffffffffu, bdw, off);
                    int   oc = __shfl_xor_sync(0xffffffffu, bcw, off);
                    if (ob < bdw || (ob == bdw && oc < bcw)) { bdw = ob; bcw = oc; }
                }
                if ((tid & 31) == ld) { bd = bdw; bc = bcw; }
            }

            const int gt = gtok0 + t;
            g_idx[gt] = bc;
            out[OFF_IDX + gt] = (float)bc;
            red_f(&g_ni[bc], 1.0f);
            float l = bd + xn;
            #pragma unroll
            for (int o = 16; o; o >>= 1) l += __shfl_xor_sync(0xffffffffu, l, o);
            if ((tid & 31) == 0) red_f(&g_loss, l);

            float* gb = g_eofxT + bc * DIM;
            const float4* xg = (const float4*)(x + (size_t)gt * DIM);
            #pragma unroll
            for (int j = 0; j < 16; j++) {
                float4 v = xg[j];
                red_v2(gb + 4 * j, v.x, v.y);
                red_v2(gb + 4 * j + 2, v.z, v.w);
            }
        }
        __syncthreads();
    }
}

// ---------------- k3: post (gather + N + M/emb, block-independent) ----------------
extern __shared__ float sPost[];

__global__ void __launch_bounds__(256)
vq_post(const float* __restrict__ Nin, const float* __restrict__ Min,
        float* __restrict__ out) {
    const int b = blockIdx.x;
    const int tid = threadIdx.x;
    const float DEC = 0.99f, OMD = 1.0f - 0.99f;

    if (b < 256) {
        // quantize gather
        float* sE = sPost;   // [512][64]
        const float4* src = (const float4*)g_embT;
        float4* dst = (float4*)sE;
        #pragma unroll
        for (int it = 0; it < 32; it++) dst[it * 256 + tid] = src[it * 256 + tid];
        __syncthreads();
        const int warp = tid >> 5, lane = tid & 31;
        const int tbase = b * 1024 + warp * 128;
        int my[4];
        #pragma unroll
        for (int i = 0; i < 4; i++) my[i] = g_idx[tbase + i * 32 + lane];
        #pragma unroll
        for (int i = 0; i < 4; i++) {
            #pragma unroll 8
            for (int s = 0; s < 32; s++) {
                int c = __shfl_sync(0xffffffffu, my[i], s);
                float2 qv = *(const float2*)&sE[c * DIM + lane * 2];
                *(float2*)&out[OFF_Q + (size_t)(tbase + i * 32 + s) * DIM + lane * 2] = qv;
            }
        }
        return;
    }

    // N_new recomputed locally (block-independent)
    float* sNn  = sPost;        // 512
    float* sSum = sPost + 512;  // 256
    #pragma unroll
    for (int h = 0; h < 2; h++) {
        int c = h * 256 + tid;
        sNn[c] = fmaf(Nin[c], DEC, OMD * g_ni[c]);
    }
    __syncthreads();
    sSum[tid] = sNn[tid] + sNn[256 + tid];
    __syncthreads();
    for (int s = 128; s > 0; s >>= 1) {
        if (tid < s) sSum[tid] += sSum[tid + s];
        __syncthreads();
    }
    const float n = sSum[0];

    if (b < 320) {
        // M_new + embedding_new, 512 elements per block
        #pragma unroll
        for (int h = 0; h < 2; h++) {
            int idx = (b - 256) * 512 + h * 256 + tid;
            int d = idx >> 9, c = idx & (CODES - 1);
            float Ns = (sNn[c] + 1e-5f) / (n + CODES * 1e-5f) * n;
            float Mn = fmaf(Min[idx], DEC, OMD * g_eofxT[c * DIM + d]);
            out[OFF_M + idx] = Mn;
            out[OFF_EMB + idx] = Mn / Ns;
        }
    } else {
        // N outputs + losses
        #pragma unroll
        for (int h = 0; h < 2; h++) {
            int c = h * 256 + tid;
            out[OFF_N + c] = sNn[c];
        }
        if (tid == 0) {
            float l = g_loss * (1.0f / 16777216.0f);
            out[OFF_QL] = l;
            out[OFF_CL] = l;
        }
    }
}

extern "C" void kernel_launch(void* const* d_in, const int* in_sizes, int n_in,
                              void* d_out, int out_size) {
    const float* x   = (const float*)d_in[0];
    const float* emb = (const float*)d_in[1];
    const float* N   = (const float*)d_in[2];
    const float* M   = (const float*)d_in[3];
    float* out = (float*)d_out;

    cudaFuncSetAttribute(vq_mma, cudaFuncAttributeMaxDynamicSharedMemorySize, SMEM_BYTES);
    cudaFuncSetAttribute(vq_post, cudaFuncAttributeMaxDynamicSharedMemorySize, 131072);

    vq_split<<<64, 512>>>(emb);
    vq_mma<<<GRID2, TPB, SMEM_BYTES>>>(x, out);
    vq_post<<<321, 256, 131072>>>(N, M, out);
}